// round 2
// baseline (speedup 1.0000x reference)
#include <cuda_runtime.h>
#include <cstdint>

#define BATCH  32
#define SMAX   222
#define S1     197
#define DMODEL 768
#define NLAYER 12
#define NHEAD  12
#define HDIM   64
#define MLPD   3072
#define POOL   10
#define SEL    5
#define PLEN   5
#define NCLS   100

// ---------------- scratch (static device allocations; harness-legal) ----------------
__device__ float g_x   [BATCH * SMAX * DMODEL];
__device__ float g_x0  [BATCH * S1   * DMODEL];
__device__ float g_h   [BATCH * SMAX * DMODEL];
__device__ float g_qkv [BATCH * SMAX * 3 * DMODEL];
__device__ float g_o   [BATCH * SMAX * DMODEL];
__device__ float g_mlp [BATCH * SMAX * MLPD];
__device__ float g_feat[BATCH * DMODEL];
__device__ float g_score[BATCH * POOL];
__device__ float g_lognorm[POOL];
__device__ float g_logwn[POOL];
__device__ int   g_topk[BATCH * SEL];

// ---------------- reductions (blockDim == 256 assumed) ----------------
__device__ __forceinline__ float block_sum256(float v, float* red) {
    int lane = threadIdx.x & 31, wid = threadIdx.x >> 5;
    #pragma unroll
    for (int o = 16; o; o >>= 1) v += __shfl_xor_sync(0xffffffffu, v, o);
    if (lane == 0) red[wid] = v;
    __syncthreads();
    float r = (lane < 8) ? red[lane] : 0.f;
    #pragma unroll
    for (int o = 4; o; o >>= 1) r += __shfl_xor_sync(0xffffffffu, r, o);
    r = __shfl_sync(0xffffffffu, r, 0);
    __syncthreads();
    return r;
}

__device__ __forceinline__ float block_max256(float v, float* red) {
    int lane = threadIdx.x & 31, wid = threadIdx.x >> 5;
    #pragma unroll
    for (int o = 16; o; o >>= 1) v = fmaxf(v, __shfl_xor_sync(0xffffffffu, v, o));
    if (lane == 0) red[wid] = v;
    __syncthreads();
    float r = (lane < 8) ? red[lane] : -1e30f;
    #pragma unroll
    for (int o = 4; o; o >>= 1) r = fmaxf(r, __shfl_xor_sync(0xffffffffu, r, o));
    r = __shfl_sync(0xffffffffu, r, 0);
    __syncthreads();
    return r;
}

// ---------------- tf32 helpers ----------------
__device__ __forceinline__ float to_tf32(float x) {
    uint32_t u;
    asm("cvt.rna.tf32.f32 %0, %1;" : "=r"(u) : "f"(x));
    return __uint_as_float(u);
}

__device__ __forceinline__ void mma_tf32(float* c, const uint32_t* a, uint32_t b0, uint32_t b1) {
    asm volatile(
        "mma.sync.aligned.m16n8k8.row.col.f32.tf32.tf32.f32 "
        "{%0,%1,%2,%3}, {%4,%5,%6,%7}, {%8,%9}, {%0,%1,%2,%3};"
        : "+f"(c[0]), "+f"(c[1]), "+f"(c[2]), "+f"(c[3])
        : "r"(a[0]), "r"(a[1]), "r"(a[2]), "r"(a[3]), "r"(b0), "r"(b1));
}

// ---------------- tensor-core GEMM: C[M,N] = A[M,K] @ W[K,N] + bias ----------------
// mode 0 = store, 1 = exact GELU then store, 2 = add into C (residual)
// Requires: N % 128 == 0, K % 32 == 0. M guarded.
#define TBM 128
#define TBN 128
#define TBK 32
#define APAD 8

__global__ void __launch_bounds__(256) tc_gemm_kernel(
    const float* __restrict__ A, const float* __restrict__ W,
    const float* __restrict__ bias, float* __restrict__ C,
    int M, int N, int K, int mode)
{
    __shared__ float As[TBK][TBM + APAD];   // [k][m], tf32-rounded
    __shared__ float Ws[TBK][TBN + APAD];   // [k][n], tf32-rounded

    int tid  = threadIdx.x;
    int warp = tid >> 5, lane = tid & 31;
    int g = lane >> 2, tig = lane & 3;
    int wm = (warp & 1) * 64;      // warp M offset (2 warps over M)
    int wn = (warp >> 1) * 32;     // warp N offset (4 warps over N)
    int row0 = blockIdx.y * TBM;
    int col0 = blockIdx.x * TBN;

    float acc[4][4][4];
    #pragma unroll
    for (int mt = 0; mt < 4; mt++)
        #pragma unroll
        for (int nt = 0; nt < 4; nt++)
            #pragma unroll
            for (int i = 0; i < 4; i++) acc[mt][nt][i] = 0.f;

    for (int k0 = 0; k0 < K; k0 += TBK) {
        // load A tile (128 rows x 32 k), transpose into As[k][m]
        #pragma unroll
        for (int i = 0; i < 4; i++) {
            int idx = tid + i * 256;          // 0..1023 float4 slots
            int r   = idx >> 3;               // 0..127
            int kc  = (idx & 7) * 4;          // 0..28
            int gm  = row0 + r;
            float4 v = make_float4(0.f, 0.f, 0.f, 0.f);
            if (gm < M) v = *reinterpret_cast<const float4*>(&A[(size_t)gm * K + k0 + kc]);
            As[kc + 0][r] = to_tf32(v.x);
            As[kc + 1][r] = to_tf32(v.y);
            As[kc + 2][r] = to_tf32(v.z);
            As[kc + 3][r] = to_tf32(v.w);
        }
        // load W tile (32 k x 128 n)
        #pragma unroll
        for (int i = 0; i < 4; i++) {
            int idx = tid + i * 256;
            int kr  = idx >> 5;               // 0..31
            int nc  = (idx & 31) * 4;         // 0..124
            float4 v = *reinterpret_cast<const float4*>(&W[(size_t)(k0 + kr) * N + col0 + nc]);
            float4 t;
            t.x = to_tf32(v.x); t.y = to_tf32(v.y); t.z = to_tf32(v.z); t.w = to_tf32(v.w);
            *reinterpret_cast<float4*>(&Ws[kr][nc]) = t;
        }
        __syncthreads();

        #pragma unroll
        for (int ks = 0; ks < 4; ks++) {
            int kk = ks * 8;
            uint32_t af[4][4];
            #pragma unroll
            for (int mt = 0; mt < 4; mt++) {
                int m0 = wm + mt * 16;
                af[mt][0] = __float_as_uint(As[kk + tig    ][m0 + g    ]);
                af[mt][1] = __float_as_uint(As[kk + tig    ][m0 + g + 8]);
                af[mt][2] = __float_as_uint(As[kk + tig + 4][m0 + g    ]);
                af[mt][3] = __float_as_uint(As[kk + tig + 4][m0 + g + 8]);
            }
            #pragma unroll
            for (int nt = 0; nt < 4; nt++) {
                int n0 = wn + nt * 8;
                uint32_t b0 = __float_as_uint(Ws[kk + tig    ][n0 + g]);
                uint32_t b1 = __float_as_uint(Ws[kk + tig + 4][n0 + g]);
                #pragma unroll
                for (int mt = 0; mt < 4; mt++)
                    mma_tf32(acc[mt][nt], af[mt], b0, b1);
            }
        }
        __syncthreads();
    }

    // epilogue
    #pragma unroll
    for (int mt = 0; mt < 4; mt++) {
        #pragma unroll
        for (int nt = 0; nt < 4; nt++) {
            int gn = col0 + wn + nt * 8 + tig * 2;
            #pragma unroll
            for (int half = 0; half < 2; half++) {
                int gm = row0 + wm + mt * 16 + g + half * 8;
                if (gm >= M) continue;
                #pragma unroll
                for (int cc = 0; cc < 2; cc++) {
                    float v = acc[mt][nt][half * 2 + cc] + bias[gn + cc];
                    if (mode == 1) v = 0.5f * v * (1.0f + erff(v * 0.70710678118654752f));
                    size_t off = (size_t)gm * N + gn + cc;
                    if (mode == 2) C[off] += v;
                    else C[off] = v;
                }
            }
        }
    }
}

// ---------------- LayerNorm over 768 (= 3*256) ----------------
__global__ void ln_kernel(const float* __restrict__ in, float* __restrict__ out,
                          const float* __restrict__ w, const float* __restrict__ b,
                          long long in_stride, long long out_stride)
{
    __shared__ float red[8];
    const float* x = in + (long long)blockIdx.x * in_stride;
    float* y = out + (long long)blockIdx.x * out_stride;
    int t = threadIdx.x;
    float v0 = x[t], v1 = x[t + 256], v2 = x[t + 512];
    float mean = block_sum256(v0 + v1 + v2, red) * (1.f / 768.f);
    float d0 = v0 - mean, d1 = v1 - mean, d2 = v2 - mean;
    float var = block_sum256(d0 * d0 + d1 * d1 + d2 * d2, red) * (1.f / 768.f);
    float rstd = rsqrtf(var + 1e-6f);
    y[t]       = d0 * rstd * w[t]       + b[t];
    y[t + 256] = d1 * rstd * w[t + 256] + b[t + 256];
    y[t + 512] = d2 * rstd * w[t + 512] + b[t + 512];
}

// ---------------- attention: one block per (q, head, batch) ----------------
__global__ void attn_kernel(const float* __restrict__ qkv, float* __restrict__ o, int S)
{
    int qi = blockIdx.x, h = blockIdx.y, b = blockIdx.z;
    __shared__ float qv[HDIM];
    __shared__ float pr[256];
    __shared__ float red[8];
    __shared__ float opart[4][HDIM];
    int tid = threadIdx.x;
    const float* base = qkv + (size_t)b * S * (3 * DMODEL);

    if (tid < HDIM) qv[tid] = base[(size_t)qi * (3 * DMODEL) + h * HDIM + tid];
    __syncthreads();

    float sc = -1e30f;
    if (tid < S) {
        const float* kp = base + (size_t)tid * (3 * DMODEL) + DMODEL + h * HDIM;
        float d = 0.f;
        #pragma unroll
        for (int i = 0; i < HDIM; i++) d += qv[i] * kp[i];
        sc = d * 0.125f;   // 64^-0.5
    }
    float mx = block_max256(sc, red);
    float e = (tid < S) ? expf(sc - mx) : 0.f;
    float sum = block_sum256(e, red);
    pr[tid] = e / sum;
    __syncthreads();

    int kg = tid >> 6, d = tid & 63;
    const float* vb = base + 2 * DMODEL + h * HDIM + d;
    float accv = 0.f;
    for (int k = kg; k < S; k += 4) accv += pr[k] * vb[(size_t)k * (3 * DMODEL)];
    opart[kg][d] = accv;
    __syncthreads();
    if (tid < HDIM) {
        float r = opart[0][tid] + opart[1][tid] + opart[2][tid] + opart[3][tid];
        o[((size_t)(b * S + qi)) * DMODEL + h * HDIM + tid] = r;
    }
}

// ---------------- patchify + embedding ----------------
__global__ void patchify_kernel(const float* __restrict__ in)
{
    size_t i = (size_t)blockIdx.x * 256 + threadIdx.x;
    if (i >= (size_t)BATCH * 196 * DMODEL) return;
    int v = (int)(i % DMODEL);
    size_t t = i / DMODEL;
    int p = (int)(t % 196);
    int b = (int)(t / 196);
    int c = v >> 8;                // / 256
    int py = (v & 255) >> 4;
    int px = v & 15;
    int gy = p / 14, gx = p % 14;
    g_mlp[i] = in[(((size_t)b * 3 + c) * 224 + gy * 16 + py) * 224 + gx * 16 + px];
}

__global__ void embed_kernel(const float* __restrict__ cls, const float* __restrict__ pos)
{
    size_t i = (size_t)blockIdx.x * 256 + threadIdx.x;
    if (i >= (size_t)BATCH * S1 * DMODEL) return;
    int d = (int)(i % DMODEL);
    size_t t = i / DMODEL;
    int s = (int)(t % S1);
    int b = (int)(t / S1);
    float v;
    if (s == 0) v = cls[d] + pos[d];
    else        v = g_o[((size_t)b * 196 + (s - 1)) * DMODEL + d] + pos[(size_t)s * DMODEL + d];
    g_x[i] = v;
    g_x0[i] = v;
}

// ---------------- routing ----------------
__global__ void pool_stats_kernel(const float* __restrict__ var)
{
    __shared__ float red[8];
    int p = blockIdx.x;
    const float* v = var + (size_t)p * DMODEL * DMODEL;
    float s = 0.f;
    for (int i = threadIdx.x; i < DMODEL * DMODEL; i += 256) { float t = v[i]; s += t * t; }
    float tot = block_sum256(s, red);
    if (threadIdx.x == 0) g_lognorm[p] = 0.25f * logf(tot);  // 0.5*log(sqrt(ss))
}

__global__ void logwn_kernel(const float* __restrict__ freq)
{
    float m = freq[0];
    for (int i = 1; i < POOL; i++) m = fmaxf(m, freq[i]);
    float w[POOL]; float ss = 0.f;
    for (int i = 0; i < POOL; i++) { w[i] = m - freq[i]; ss += w[i] * w[i]; }
    float nz = fmaxf(sqrtf(ss), 1e-12f);
    for (int i = 0; i < POOL; i++) g_logwn[i] = logf(fmaxf(w[i] / nz, 1e-30f));
}

__global__ void quad_kernel(const float* __restrict__ keys, const float* __restrict__ inv_var)
{
    __shared__ float diff[DMODEL];
    __shared__ float red[8];
    int b = blockIdx.x, p = blockIdx.y;
    for (int i = threadIdx.x; i < DMODEL; i += 256)
        diff[i] = g_feat[b * DMODEL + i] - keys[p * DMODEL + i];
    __syncthreads();
    const float* M = inv_var + (size_t)p * DMODEL * DMODEL;
    float acc = 0.f;
    for (int d = threadIdx.x; d < DMODEL; d += 256) {
        const float* row = M + (size_t)d * DMODEL;
        float t = 0.f;
        for (int e = 0; e < DMODEL; e++) t += row[e] * diff[e];
        acc += diff[d] * t;
    }
    float quad = block_sum256(acc, red);
    if (threadIdx.x == 0)
        g_score[b * POOL + p] = -0.5f * quad + g_lognorm[p] + g_logwn[p];
}

__global__ void topk_kernel()
{
    int b = threadIdx.x;
    if (b >= BATCH) return;
    float s[POOL]; bool used[POOL];
    for (int p = 0; p < POOL; p++) { s[p] = g_score[b * POOL + p]; used[p] = false; }
    for (int i = 0; i < SEL; i++) {
        int best = 0; float bv = 3.0e38f;
        for (int p = 0; p < POOL; p++)
            if (!used[p] && s[p] < bv) { bv = s[p]; best = p; }   // strict < : lowest index on tie
        used[best] = true;
        g_topk[b * SEL + i] = best;
    }
}

__global__ void build_sx_kernel(const float* __restrict__ prompts, const float* __restrict__ pos)
{
    size_t i = (size_t)blockIdx.x * 256 + threadIdx.x;
    if (i >= (size_t)BATCH * SMAX * DMODEL) return;
    int d = (int)(i % DMODEL);
    size_t t = i / DMODEL;
    int s = (int)(t % SMAX);
    int b = (int)(t / SMAX);
    float v;
    if (s == 0) {
        v = g_x0[(size_t)b * S1 * DMODEL + d];
    } else if (s <= SEL * PLEN) {
        int idx = s - 1;
        int pi = idx / PLEN, j = idx % PLEN;
        int pool = g_topk[b * SEL + pi];
        v = prompts[((size_t)pool * PLEN + j) * DMODEL + d] + pos[d];
    } else {
        v = g_x0[((size_t)b * S1 + (s - SEL * PLEN)) * DMODEL + d];
    }
    g_x[i] = v;
}

// ---------------- epilogue ----------------
__global__ void feat_kernel()
{
    int i = blockIdx.x * 256 + threadIdx.x;
    if (i >= BATCH * DMODEL) return;
    int b = i / DMODEL, d = i % DMODEL;
    float s = 0.f;
    for (int t = 1; t <= SEL * PLEN; t++)
        s += g_h[((size_t)b * SMAX + t) * DMODEL + d];
    g_feat[i] = s * (1.f / (SEL * PLEN));
}

__global__ void head_kernel(const float* __restrict__ hw, const float* __restrict__ hb,
                            float* __restrict__ out)
{
    int i = blockIdx.x * 256 + threadIdx.x;
    if (i >= BATCH * NCLS) return;
    int b = i / NCLS, n = i % NCLS;
    float acc = hb[n];
    for (int k = 0; k < DMODEL; k++) acc += g_feat[b * DMODEL + k] * hw[k * NCLS + n];
    out[i] = acc;
}

// ---------------- host orchestration ----------------
static void run_vit(int S, int M,
    const float* ln1w, const float* ln1b, const float* qkvw, const float* qkvb,
    const float* pw, const float* pb, const float* ln2w, const float* ln2b,
    const float* f1w, const float* f1b, const float* f2w, const float* f2b,
    float* px, float* ph, float* pqkv, float* po, float* pmlp)
{
    int gy = (M + TBM - 1) / TBM;
    for (int l = 0; l < NLAYER; l++) {
        ln_kernel<<<M, 256>>>(px, ph, ln1w + (size_t)l * DMODEL, ln1b + (size_t)l * DMODEL, DMODEL, DMODEL);
        tc_gemm_kernel<<<dim3(3 * DMODEL / TBN, gy), 256>>>(ph, qkvw + (size_t)l * DMODEL * 3 * DMODEL,
                                                            qkvb + (size_t)l * 3 * DMODEL, pqkv, M, 3 * DMODEL, DMODEL, 0);
        attn_kernel<<<dim3(S, NHEAD, BATCH), 256>>>(pqkv, po, S);
        tc_gemm_kernel<<<dim3(DMODEL / TBN, gy), 256>>>(po, pw + (size_t)l * DMODEL * DMODEL,
                                                        pb + (size_t)l * DMODEL, px, M, DMODEL, DMODEL, 2);
        ln_kernel<<<M, 256>>>(px, ph, ln2w + (size_t)l * DMODEL, ln2b + (size_t)l * DMODEL, DMODEL, DMODEL);
        tc_gemm_kernel<<<dim3(MLPD / TBN, gy), 256>>>(ph, f1w + (size_t)l * DMODEL * MLPD,
                                                      f1b + (size_t)l * MLPD, pmlp, M, MLPD, DMODEL, 1);
        tc_gemm_kernel<<<dim3(DMODEL / TBN, gy), 256>>>(pmlp, f2w + (size_t)l * MLPD * DMODEL,
                                                        f2b + (size_t)l * DMODEL, px, M, DMODEL, MLPD, 2);
    }
}

extern "C" void kernel_launch(void* const* d_in, const int* in_sizes, int n_in,
                              void* d_out, int out_size)
{
    const float* inputs    = (const float*)d_in[0];
    const float* patch_w   = (const float*)d_in[1];
    const float* patch_b   = (const float*)d_in[2];
    const float* cls_token = (const float*)d_in[3];
    const float* pos_embed = (const float*)d_in[4];
    const float* ln1_w = (const float*)d_in[5];
    const float* ln1_b = (const float*)d_in[6];
    const float* qkv_w = (const float*)d_in[7];
    const float* qkv_b = (const float*)d_in[8];
    const float* proj_w = (const float*)d_in[9];
    const float* proj_b = (const float*)d_in[10];
    const float* ln2_w = (const float*)d_in[11];
    const float* ln2_b = (const float*)d_in[12];
    const float* fc1_w = (const float*)d_in[13];
    const float* fc1_b = (const float*)d_in[14];
    const float* fc2_w = (const float*)d_in[15];
    const float* fc2_b = (const float*)d_in[16];
    const float* norm_w = (const float*)d_in[17];
    const float* norm_b = (const float*)d_in[18];
    const float* head_w = (const float*)d_in[19];
    const float* head_b = (const float*)d_in[20];
    const float* key_pool = (const float*)d_in[21];
    const float* frequency = (const float*)d_in[22];
    const float* prompts = (const float*)d_in[23];
    const float* variance = (const float*)d_in[24];
    const float* inv_variance = (const float*)d_in[25];

    float *px, *ph, *pqkv, *po, *pmlp, *pfeat;
    cudaGetSymbolAddress((void**)&px,   g_x);
    cudaGetSymbolAddress((void**)&ph,   g_h);
    cudaGetSymbolAddress((void**)&pqkv, g_qkv);
    cudaGetSymbolAddress((void**)&po,   g_o);
    cudaGetSymbolAddress((void**)&pmlp, g_mlp);
    cudaGetSymbolAddress((void**)&pfeat, g_feat);

    // 1) patch embed
    patchify_kernel<<<(BATCH * 196 * DMODEL + 255) / 256, 256>>>(inputs);
    tc_gemm_kernel<<<dim3(DMODEL / TBN, (BATCH * 196 + TBM - 1) / TBM), 256>>>(
        pmlp, patch_w, patch_b, po, BATCH * 196, DMODEL, DMODEL, 0);
    embed_kernel<<<(BATCH * S1 * DMODEL + 255) / 256, 256>>>(cls_token, pos_embed);

    // 2) first ViT pass (S=197)
    run_vit(S1, BATCH * S1, ln1_w, ln1_b, qkv_w, qkv_b, proj_w, proj_b,
            ln2_w, ln2_b, fc1_w, fc1_b, fc2_w, fc2_b, px, ph, pqkv, po, pmlp);

    // 3) routing: LN on CLS token only -> g_feat, then Mahalanobis scores -> topk
    ln_kernel<<<BATCH, 256>>>(px, pfeat, norm_w, norm_b, (long long)S1 * DMODEL, DMODEL);
    pool_stats_kernel<<<POOL, 256>>>(variance);
    logwn_kernel<<<1, 1>>>(frequency);
    quad_kernel<<<dim3(BATCH, POOL), 256>>>(key_pool, inv_variance);
    topk_kernel<<<1, 32>>>();

    // 4) splice prompts into original embedding (S=222)
    build_sx_kernel<<<(BATCH * SMAX * DMODEL + 255) / 256, 256>>>(prompts, pos_embed);

    // 5) second ViT pass (S=222)
    run_vit(SMAX, BATCH * SMAX, ln1_w, ln1_b, qkv_w, qkv_b, proj_w, proj_b,
            ln2_w, ln2_b, fc1_w, fc1_b, fc2_w, fc2_b, px, ph, pqkv, po, pmlp);

    // 6) final LN, mean over prompt tokens, head
    ln_kernel<<<BATCH * SMAX, 256>>>(px, ph, norm_w, norm_b, DMODEL, DMODEL);
    feat_kernel<<<(BATCH * DMODEL + 255) / 256, 256>>>();
    head_kernel<<<(BATCH * NCLS + 255) / 256, 256>>>(head_w, head_b, (float*)d_out);
}

// round 4
// speedup vs baseline: 4.4709x; 4.4709x over previous
#include <cuda_runtime.h>
#include <cstdint>

#define BATCH  32
#define SMAX   222
#define S1     197
#define DMODEL 768
#define NLAYER 12
#define NHEAD  12
#define HDIM   64
#define MLPD   3072
#define POOL   10
#define SEL    5
#define PLEN   5
#define NCLS   100
#define PSTRIDE 224

// ---------------- scratch (static device allocations; harness-legal) ----------------
__device__ float g_x   [BATCH * SMAX * DMODEL];
__device__ float g_x0  [BATCH * S1   * DMODEL];
__device__ float g_h   [BATCH * SMAX * DMODEL];
__device__ float g_qkv [BATCH * SMAX * 3 * DMODEL];
__device__ float g_o   [BATCH * SMAX * DMODEL];
__device__ float g_mlp [BATCH * SMAX * MLPD];
__device__ float g_p   [BATCH * NHEAD * PSTRIDE * PSTRIDE];
__device__ float g_feat[BATCH * DMODEL];
__device__ float g_score[BATCH * POOL];
__device__ float g_lognorm[POOL];
__device__ float g_logwn[POOL];
__device__ int   g_topk[BATCH * SEL];

// ---------------- reductions (blockDim == 256 assumed) ----------------
__device__ __forceinline__ float block_sum256(float v, float* red) {
    int lane = threadIdx.x & 31, wid = threadIdx.x >> 5;
    #pragma unroll
    for (int o = 16; o; o >>= 1) v += __shfl_xor_sync(0xffffffffu, v, o);
    if (lane == 0) red[wid] = v;
    __syncthreads();
    float r = (lane < 8) ? red[lane] : 0.f;
    #pragma unroll
    for (int o = 4; o; o >>= 1) r += __shfl_xor_sync(0xffffffffu, r, o);
    r = __shfl_sync(0xffffffffu, r, 0);
    __syncthreads();
    return r;
}

__device__ __forceinline__ float block_max256(float v, float* red) {
    int lane = threadIdx.x & 31, wid = threadIdx.x >> 5;
    #pragma unroll
    for (int o = 16; o; o >>= 1) v = fmaxf(v, __shfl_xor_sync(0xffffffffu, v, o));
    if (lane == 0) red[wid] = v;
    __syncthreads();
    float r = (lane < 8) ? red[lane] : -1e30f;
    #pragma unroll
    for (int o = 4; o; o >>= 1) r = fmaxf(r, __shfl_xor_sync(0xffffffffu, r, o));
    r = __shfl_sync(0xffffffffu, r, 0);
    __syncthreads();
    return r;
}

// ---------------- tf32 helpers ----------------
__device__ __forceinline__ float to_tf32(float x) {
    uint32_t u;
    asm("cvt.rna.tf32.f32 %0, %1;" : "=r"(u) : "f"(x));
    return __uint_as_float(u);
}

__device__ __forceinline__ void mma_tf32(float* c, const uint32_t* a, uint32_t b0, uint32_t b1) {
    asm volatile(
        "mma.sync.aligned.m16n8k8.row.col.f32.tf32.tf32.f32 "
        "{%0,%1,%2,%3}, {%4,%5,%6,%7}, {%8,%9}, {%0,%1,%2,%3};"
        : "+f"(c[0]), "+f"(c[1]), "+f"(c[2]), "+f"(c[3])
        : "r"(a[0]), "r"(a[1]), "r"(a[2]), "r"(a[3]), "r"(b0), "r"(b1));
}

// ---------------- tensor-core GEMM: C[M,N] = A[M,K] @ W[K,N] + bias ----------------
// mode 0 = store, 1 = exact GELU then store, 2 = add into C (residual)
#define TBM 128
#define TBN 128
#define TBK 32
#define APAD 8

__global__ void __launch_bounds__(256) tc_gemm_kernel(
    const float* __restrict__ A, const float* __restrict__ W,
    const float* __restrict__ bias, float* __restrict__ C,
    int M, int N, int K, int mode)
{
    __shared__ float As[TBK][TBM + APAD];
    __shared__ float Ws[TBK][TBN + APAD];

    int tid  = threadIdx.x;
    int warp = tid >> 5, lane = tid & 31;
    int g = lane >> 2, tig = lane & 3;
    int wm = (warp & 1) * 64;
    int wn = (warp >> 1) * 32;
    int row0 = blockIdx.y * TBM;
    int col0 = blockIdx.x * TBN;

    float acc[4][4][4];
    #pragma unroll
    for (int mt = 0; mt < 4; mt++)
        #pragma unroll
        for (int nt = 0; nt < 4; nt++)
            #pragma unroll
            for (int i = 0; i < 4; i++) acc[mt][nt][i] = 0.f;

    for (int k0 = 0; k0 < K; k0 += TBK) {
        #pragma unroll
        for (int i = 0; i < 4; i++) {
            int idx = tid + i * 256;
            int r   = idx >> 3;
            int kc  = (idx & 7) * 4;
            int gm  = row0 + r;
            float4 v = make_float4(0.f, 0.f, 0.f, 0.f);
            if (gm < M) v = *reinterpret_cast<const float4*>(&A[(size_t)gm * K + k0 + kc]);
            As[kc + 0][r] = to_tf32(v.x);
            As[kc + 1][r] = to_tf32(v.y);
            As[kc + 2][r] = to_tf32(v.z);
            As[kc + 3][r] = to_tf32(v.w);
        }
        #pragma unroll
        for (int i = 0; i < 4; i++) {
            int idx = tid + i * 256;
            int kr  = idx >> 5;
            int nc  = (idx & 31) * 4;
            float4 v = *reinterpret_cast<const float4*>(&W[(size_t)(k0 + kr) * N + col0 + nc]);
            float4 t;
            t.x = to_tf32(v.x); t.y = to_tf32(v.y); t.z = to_tf32(v.z); t.w = to_tf32(v.w);
            *reinterpret_cast<float4*>(&Ws[kr][nc]) = t;
        }
        __syncthreads();

        #pragma unroll
        for (int ks = 0; ks < 4; ks++) {
            int kk = ks * 8;
            uint32_t af[4][4];
            #pragma unroll
            for (int mt = 0; mt < 4; mt++) {
                int m0 = wm + mt * 16;
                af[mt][0] = __float_as_uint(As[kk + tig    ][m0 + g    ]);
                af[mt][1] = __float_as_uint(As[kk + tig    ][m0 + g + 8]);
                af[mt][2] = __float_as_uint(As[kk + tig + 4][m0 + g    ]);
                af[mt][3] = __float_as_uint(As[kk + tig + 4][m0 + g + 8]);
            }
            #pragma unroll
            for (int nt = 0; nt < 4; nt++) {
                int n0 = wn + nt * 8;
                uint32_t b0 = __float_as_uint(Ws[kk + tig    ][n0 + g]);
                uint32_t b1 = __float_as_uint(Ws[kk + tig + 4][n0 + g]);
                #pragma unroll
                for (int mt = 0; mt < 4; mt++)
                    mma_tf32(acc[mt][nt], af[mt], b0, b1);
            }
        }
        __syncthreads();
    }

    #pragma unroll
    for (int mt = 0; mt < 4; mt++) {
        #pragma unroll
        for (int nt = 0; nt < 4; nt++) {
            int gn = col0 + wn + nt * 8 + tig * 2;
            #pragma unroll
            for (int half = 0; half < 2; half++) {
                int gm = row0 + wm + mt * 16 + g + half * 8;
                if (gm >= M) continue;
                #pragma unroll
                for (int cc = 0; cc < 2; cc++) {
                    float v = acc[mt][nt][half * 2 + cc] + bias[gn + cc];
                    if (mode == 1) v = 0.5f * v * (1.0f + erff(v * 0.70710678118654752f));
                    size_t off = (size_t)gm * N + gn + cc;
                    if (mode == 2) C[off] += v;
                    else C[off] = v;
                }
            }
        }
    }
}

// ---------------- LayerNorm over 768 (= 3*256) ----------------
__global__ void ln_kernel(const float* __restrict__ in, float* __restrict__ out,
                          const float* __restrict__ w, const float* __restrict__ b,
                          long long in_stride, long long out_stride)
{
    __shared__ float red[8];
    const float* x = in + (long long)blockIdx.x * in_stride;
    float* y = out + (long long)blockIdx.x * out_stride;
    int t = threadIdx.x;
    float v0 = x[t], v1 = x[t + 256], v2 = x[t + 512];
    float mean = block_sum256(v0 + v1 + v2, red) * (1.f / 768.f);
    float d0 = v0 - mean, d1 = v1 - mean, d2 = v2 - mean;
    float var = block_sum256(d0 * d0 + d1 * d1 + d2 * d2, red) * (1.f / 768.f);
    float rstd = rsqrtf(var + 1e-6f);
    y[t]       = d0 * rstd * w[t]       + b[t];
    y[t + 256] = d1 * rstd * w[t + 256] + b[t + 256];
    y[t + 512] = d2 * rstd * w[t + 512] + b[t + 512];
}

// ---------------- attention (coalesced, smem-tiled, P materialized) ----------------
// NOTE: smem rows padded to 68 floats (multiple of 4 -> float4-aligned row stride).
#define SPAD 68

__global__ void __launch_bounds__(256) score_kernel(const float* __restrict__ qkv, int S)
{
    __shared__ float Qs[32][SPAD];
    __shared__ float KsT[64][SPAD];   // [d][k] transposed
    int q0 = blockIdx.x * 32, h = blockIdx.y, b = blockIdx.z;
    int tid = threadIdx.x;
    int q = tid >> 3, kg = tid & 7;
    const float* base = qkv + (size_t)b * S * (3 * DMODEL) + h * HDIM;
    float* prow = g_p + (((size_t)b * NHEAD + h) * PSTRIDE) * PSTRIDE;

    // load Q tile [32 x 64] (coalesced float4)
    #pragma unroll
    for (int i = 0; i < 2; i++) {
        int slot = tid + i * 256;          // 0..511 float4 slots
        int r = slot >> 4, c4 = (slot & 15) * 4;
        int gq = q0 + r;
        float4 v = make_float4(0.f, 0.f, 0.f, 0.f);
        if (gq < S) v = *reinterpret_cast<const float4*>(&base[(size_t)gq * (3 * DMODEL) + c4]);
        *reinterpret_cast<float4*>(&Qs[r][c4]) = v;
    }

    int ntile = (S + 63) >> 6;
    for (int kt = 0; kt < ntile; kt++) {
        int k0 = kt * 64;
        // load K tile [64 x 64] transposed into KsT[d][k] (scalar stores)
        #pragma unroll
        for (int i = 0; i < 4; i++) {
            int slot = tid + i * 256;      // 0..1023 float4 slots
            int r = slot >> 4, c4 = (slot & 15) * 4;
            int gk = k0 + r;
            float4 v = make_float4(0.f, 0.f, 0.f, 0.f);
            if (gk < S) v = *reinterpret_cast<const float4*>(&base[(size_t)gk * (3 * DMODEL) + DMODEL + c4]);
            KsT[c4 + 0][r] = v.x;
            KsT[c4 + 1][r] = v.y;
            KsT[c4 + 2][r] = v.z;
            KsT[c4 + 3][r] = v.w;
        }
        __syncthreads();

        float acc[8];
        #pragma unroll
        for (int j = 0; j < 8; j++) acc[j] = 0.f;
        #pragma unroll
        for (int d = 0; d < HDIM; d++) {
            float qa = Qs[q][d];
            const float* kr = &KsT[d][kg * 8];
            #pragma unroll
            for (int j = 0; j < 8; j++) acc[j] += qa * kr[j];
        }
        int gq = q0 + q;
        if (gq < S) {
            float* pw = prow + (size_t)gq * PSTRIDE + k0 + kg * 8;
            #pragma unroll
            for (int j = 0; j < 8; j++) {
                int gk = k0 + kg * 8 + j;
                if (gk < S) pw[j] = acc[j] * 0.125f;
            }
        }
        __syncthreads();
    }
}

// softmax over one row (block per (q,h,b))
__global__ void softmax_kernel(int S)
{
    __shared__ float red[8];
    int q = blockIdx.x, h = blockIdx.y, b = blockIdx.z;
    float* prow = g_p + ((((size_t)b * NHEAD + h) * PSTRIDE) + q) * PSTRIDE;
    int t = threadIdx.x;
    float v = (t < S) ? prow[t] : -1e30f;
    float mx = block_max256(v, red);
    float e = (t < S) ? expf(v - mx) : 0.f;
    float sum = block_sum256(e, red);
    if (t < S) prow[t] = e / sum;
}

// pv_kernel: O tile [32 q x 64 d] per block; thread (q = tid/8, dg = tid%8)
__global__ void __launch_bounds__(256) pv_kernel(const float* __restrict__ qkv,
                                                 float* __restrict__ o, int S)
{
    __shared__ float Ps[32][SPAD];
    __shared__ float Vs[64][SPAD];
    int q0 = blockIdx.x * 32, h = blockIdx.y, b = blockIdx.z;
    int tid = threadIdx.x;
    int q = tid >> 3, dg = tid & 7;
    const float* vbase = qkv + (size_t)b * S * (3 * DMODEL) + 2 * DMODEL + h * HDIM;
    const float* prow = g_p + (((size_t)b * NHEAD + h) * PSTRIDE) * PSTRIDE;

    float acc[8];
    #pragma unroll
    for (int j = 0; j < 8; j++) acc[j] = 0.f;

    int ntile = (S + 63) >> 6;
    for (int kt = 0; kt < ntile; kt++) {
        int k0 = kt * 64;
        // load P tile [32 q x 64 k]
        #pragma unroll
        for (int i = 0; i < 2; i++) {
            int slot = tid + i * 256;
            int r = slot >> 4, c4 = (slot & 15) * 4;
            int gq = q0 + r;
            float4 v = make_float4(0.f, 0.f, 0.f, 0.f);
            if (gq < S) {
                #pragma unroll
                for (int c = 0; c < 4; c++) {
                    int gk = k0 + c4 + c;
                    ((float*)&v)[c] = (gk < S) ? prow[(size_t)gq * PSTRIDE + gk] : 0.f;
                }
            }
            *reinterpret_cast<float4*>(&Ps[r][c4]) = v;
        }
        // load V tile [64 k x 64 d]
        #pragma unroll
        for (int i = 0; i < 4; i++) {
            int slot = tid + i * 256;
            int r = slot >> 4, c4 = (slot & 15) * 4;
            int gk = k0 + r;
            float4 v = make_float4(0.f, 0.f, 0.f, 0.f);
            if (gk < S) v = *reinterpret_cast<const float4*>(&vbase[(size_t)gk * (3 * DMODEL) + c4]);
            *reinterpret_cast<float4*>(&Vs[r][c4]) = v;
        }
        __syncthreads();

        #pragma unroll
        for (int k = 0; k < 64; k++) {
            float p = Ps[q][k];
            const float* vr = &Vs[k][dg * 8];
            #pragma unroll
            for (int j = 0; j < 8; j++) acc[j] += p * vr[j];
        }
        __syncthreads();
    }

    int gq = q0 + q;
    if (gq < S) {
        float* ow = o + ((size_t)(b * S + gq)) * DMODEL + h * HDIM + dg * 8;
        #pragma unroll
        for (int j = 0; j < 8; j++) ow[j] = acc[j];
    }
}

// ---------------- patchify + embedding ----------------
__global__ void patchify_kernel(const float* __restrict__ in)
{
    size_t i = (size_t)blockIdx.x * 256 + threadIdx.x;
    if (i >= (size_t)BATCH * 196 * DMODEL) return;
    int v = (int)(i % DMODEL);
    size_t t = i / DMODEL;
    int p = (int)(t % 196);
    int b = (int)(t / 196);
    int c = v >> 8;
    int py = (v & 255) >> 4;
    int px = v & 15;
    int gy = p / 14, gx = p % 14;
    g_mlp[i] = in[(((size_t)b * 3 + c) * 224 + gy * 16 + py) * 224 + gx * 16 + px];
}

__global__ void embed_kernel(const float* __restrict__ cls, const float* __restrict__ pos)
{
    size_t i = (size_t)blockIdx.x * 256 + threadIdx.x;
    if (i >= (size_t)BATCH * S1 * DMODEL) return;
    int d = (int)(i % DMODEL);
    size_t t = i / DMODEL;
    int s = (int)(t % S1);
    int b = (int)(t / S1);
    float v;
    if (s == 0) v = cls[d] + pos[d];
    else        v = g_o[((size_t)b * 196 + (s - 1)) * DMODEL + d] + pos[(size_t)s * DMODEL + d];
    g_x[i] = v;
    g_x0[i] = v;
}

// ---------------- routing ----------------
__global__ void pool_stats_kernel(const float* __restrict__ var)
{
    __shared__ float red[8];
    int p = blockIdx.x;
    const float* v = var + (size_t)p * DMODEL * DMODEL;
    float s = 0.f;
    for (int i = threadIdx.x; i < DMODEL * DMODEL; i += 256) { float t = v[i]; s += t * t; }
    float tot = block_sum256(s, red);
    if (threadIdx.x == 0) g_lognorm[p] = 0.25f * logf(tot);
}

__global__ void logwn_kernel(const float* __restrict__ freq)
{
    float m = freq[0];
    for (int i = 1; i < POOL; i++) m = fmaxf(m, freq[i]);
    float w[POOL]; float ss = 0.f;
    for (int i = 0; i < POOL; i++) { w[i] = m - freq[i]; ss += w[i] * w[i]; }
    float nz = fmaxf(sqrtf(ss), 1e-12f);
    for (int i = 0; i < POOL; i++) g_logwn[i] = logf(fmaxf(w[i] / nz, 1e-30f));
}

// coalesced: thread e accumulates column e over all rows d
__global__ void quad_kernel(const float* __restrict__ keys, const float* __restrict__ inv_var)
{
    __shared__ float diff[DMODEL];
    __shared__ float red[8];
    int b = blockIdx.x, p = blockIdx.y;
    for (int i = threadIdx.x; i < DMODEL; i += 256)
        diff[i] = g_feat[b * DMODEL + i] - keys[p * DMODEL + i];
    __syncthreads();
    const float* M = inv_var + (size_t)p * DMODEL * DMODEL;
    float acc = 0.f;
    #pragma unroll
    for (int ei = 0; ei < 3; ei++) {
        int e = threadIdx.x + ei * 256;
        float inner = 0.f;
        for (int d = 0; d < DMODEL; d++)
            inner += diff[d] * M[(size_t)d * DMODEL + e];
        acc += inner * diff[e];
    }
    float quad = block_sum256(acc, red);
    if (threadIdx.x == 0)
        g_score[b * POOL + p] = -0.5f * quad + g_lognorm[p] + g_logwn[p];
}

__global__ void topk_kernel()
{
    int b = threadIdx.x;
    if (b >= BATCH) return;
    float s[POOL]; bool used[POOL];
    for (int p = 0; p < POOL; p++) { s[p] = g_score[b * POOL + p]; used[p] = false; }
    for (int i = 0; i < SEL; i++) {
        int best = 0; float bv = 3.0e38f;
        for (int p = 0; p < POOL; p++)
            if (!used[p] && s[p] < bv) { bv = s[p]; best = p; }
        used[best] = true;
        g_topk[b * SEL + i] = best;
    }
}

__global__ void build_sx_kernel(const float* __restrict__ prompts, const float* __restrict__ pos)
{
    size_t i = (size_t)blockIdx.x * 256 + threadIdx.x;
    if (i >= (size_t)BATCH * SMAX * DMODEL) return;
    int d = (int)(i % DMODEL);
    size_t t = i / DMODEL;
    int s = (int)(t % SMAX);
    int b = (int)(t / SMAX);
    float v;
    if (s == 0) {
        v = g_x0[(size_t)b * S1 * DMODEL + d];
    } else if (s <= SEL * PLEN) {
        int idx = s - 1;
        int pi = idx / PLEN, j = idx % PLEN;
        int pool = g_topk[b * SEL + pi];
        v = prompts[((size_t)pool * PLEN + j) * DMODEL + d] + pos[d];
    } else {
        v = g_x0[((size_t)b * S1 + (s - SEL * PLEN)) * DMODEL + d];
    }
    g_x[i] = v;
}

// ---------------- epilogue ----------------
__global__ void feat_kernel()
{
    int i = blockIdx.x * 256 + threadIdx.x;
    if (i >= BATCH * DMODEL) return;
    int b = i / DMODEL, d = i % DMODEL;
    float s = 0.f;
    for (int t = 1; t <= SEL * PLEN; t++)
        s += g_h[((size_t)b * SMAX + t) * DMODEL + d];
    g_feat[i] = s * (1.f / (SEL * PLEN));
}

__global__ void head_kernel(const float* __restrict__ hw, const float* __restrict__ hb,
                            float* __restrict__ out)
{
    int i = blockIdx.x * 256 + threadIdx.x;
    if (i >= BATCH * NCLS) return;
    int b = i / NCLS, n = i % NCLS;
    float acc = hb[n];
    for (int k = 0; k < DMODEL; k++) acc += g_feat[b * DMODEL + k] * hw[k * NCLS + n];
    out[i] = acc;
}

// ---------------- host orchestration ----------------
static void run_vit(int S, int M,
    const float* ln1w, const float* ln1b, const float* qkvw, const float* qkvb,
    const float* pw, const float* pb, const float* ln2w, const float* ln2b,
    const float* f1w, const float* f1b, const float* f2w, const float* f2b,
    float* px, float* ph, float* pqkv, float* po, float* pmlp)
{
    int gy = (M + TBM - 1) / TBM;
    int qt = (S + 31) / 32;
    for (int l = 0; l < NLAYER; l++) {
        ln_kernel<<<M, 256>>>(px, ph, ln1w + (size_t)l * DMODEL, ln1b + (size_t)l * DMODEL, DMODEL, DMODEL);
        tc_gemm_kernel<<<dim3(3 * DMODEL / TBN, gy), 256>>>(ph, qkvw + (size_t)l * DMODEL * 3 * DMODEL,
                                                            qkvb + (size_t)l * 3 * DMODEL, pqkv, M, 3 * DMODEL, DMODEL, 0);
        score_kernel<<<dim3(qt, NHEAD, BATCH), 256>>>(pqkv, S);
        softmax_kernel<<<dim3(S, NHEAD, BATCH), 256>>>(S);
        pv_kernel<<<dim3(qt, NHEAD, BATCH), 256>>>(pqkv, po, S);
        tc_gemm_kernel<<<dim3(DMODEL / TBN, gy), 256>>>(po, pw + (size_t)l * DMODEL * DMODEL,
                                                        pb + (size_t)l * DMODEL, px, M, DMODEL, DMODEL, 2);
        ln_kernel<<<M, 256>>>(px, ph, ln2w + (size_t)l * DMODEL, ln2b + (size_t)l * DMODEL, DMODEL, DMODEL);
        tc_gemm_kernel<<<dim3(MLPD / TBN, gy), 256>>>(ph, f1w + (size_t)l * DMODEL * MLPD,
                                                      f1b + (size_t)l * MLPD, pmlp, M, MLPD, DMODEL, 1);
        tc_gemm_kernel<<<dim3(DMODEL / TBN, gy), 256>>>(pmlp, f2w + (size_t)l * MLPD * DMODEL,
                                                        f2b + (size_t)l * DMODEL, px, M, DMODEL, MLPD, 2);
    }
}

extern "C" void kernel_launch(void* const* d_in, const int* in_sizes, int n_in,
                              void* d_out, int out_size)
{
    const float* inputs    = (const float*)d_in[0];
    const float* patch_w   = (const float*)d_in[1];
    const float* patch_b   = (const float*)d_in[2];
    const float* cls_token = (const float*)d_in[3];
    const float* pos_embed = (const float*)d_in[4];
    const float* ln1_w = (const float*)d_in[5];
    const float* ln1_b = (const float*)d_in[6];
    const float* qkv_w = (const float*)d_in[7];
    const float* qkv_b = (const float*)d_in[8];
    const float* proj_w = (const float*)d_in[9];
    const float* proj_b = (const float*)d_in[10];
    const float* ln2_w = (const float*)d_in[11];
    const float* ln2_b = (const float*)d_in[12];
    const float* fc1_w = (const float*)d_in[13];
    const float* fc1_b = (const float*)d_in[14];
    const float* fc2_w = (const float*)d_in[15];
    const float* fc2_b = (const float*)d_in[16];
    const float* norm_w = (const float*)d_in[17];
    const float* norm_b = (const float*)d_in[18];
    const float* head_w = (const float*)d_in[19];
    const float* head_b = (const float*)d_in[20];
    const float* key_pool = (const float*)d_in[21];
    const float* frequency = (const float*)d_in[22];
    const float* prompts = (const float*)d_in[23];
    const float* variance = (const float*)d_in[24];
    const float* inv_variance = (const float*)d_in[25];

    float *px, *ph, *pqkv, *po, *pmlp, *pfeat;
    cudaGetSymbolAddress((void**)&px,   g_x);
    cudaGetSymbolAddress((void**)&ph,   g_h);
    cudaGetSymbolAddress((void**)&pqkv, g_qkv);
    cudaGetSymbolAddress((void**)&po,   g_o);
    cudaGetSymbolAddress((void**)&pmlp, g_mlp);
    cudaGetSymbolAddress((void**)&pfeat, g_feat);

    // 1) patch embed
    patchify_kernel<<<(BATCH * 196 * DMODEL + 255) / 256, 256>>>(inputs);
    tc_gemm_kernel<<<dim3(DMODEL / TBN, (BATCH * 196 + TBM - 1) / TBM), 256>>>(
        pmlp, patch_w, patch_b, po, BATCH * 196, DMODEL, DMODEL, 0);
    embed_kernel<<<(BATCH * S1 * DMODEL + 255) / 256, 256>>>(cls_token, pos_embed);

    // 2) first ViT pass (S=197)
    run_vit(S1, BATCH * S1, ln1_w, ln1_b, qkv_w, qkv_b, proj_w, proj_b,
            ln2_w, ln2_b, fc1_w, fc1_b, fc2_w, fc2_b, px, ph, pqkv, po, pmlp);

    // 3) routing
    ln_kernel<<<BATCH, 256>>>(px, pfeat, norm_w, norm_b, (long long)S1 * DMODEL, DMODEL);
    pool_stats_kernel<<<POOL, 256>>>(variance);
    logwn_kernel<<<1, 1>>>(frequency);
    quad_kernel<<<dim3(BATCH, POOL), 256>>>(key_pool, inv_variance);
    topk_kernel<<<1, 32>>>();

    // 4) splice prompts (S=222)
    build_sx_kernel<<<(BATCH * SMAX * DMODEL + 255) / 256, 256>>>(prompts, pos_embed);

    // 5) second ViT pass (S=222)
    run_vit(SMAX, BATCH * SMAX, ln1_w, ln1_b, qkv_w, qkv_b, proj_w, proj_b,
            ln2_w, ln2_b, fc1_w, fc1_b, fc2_w, fc2_b, px, ph, pqkv, po, pmlp);

    // 6) final LN, mean over prompt tokens, head
    ln_kernel<<<BATCH * SMAX, 256>>>(px, ph, norm_w, norm_b, DMODEL, DMODEL);
    feat_kernel<<<(BATCH * DMODEL + 255) / 256, 256>>>();
    head_kernel<<<(BATCH * NCLS + 255) / 256, 256>>>(head_w, head_b, (float*)d_out);
}

// round 6
// speedup vs baseline: 5.1993x; 1.1629x over previous
#include <cuda_runtime.h>
#include <cstdint>

#define BATCH  32
#define SMAX   222
#define S1     197
#define DMODEL 768
#define NLAYER 12
#define NHEAD  12
#define HDIM   64
#define MLPD   3072
#define POOL   10
#define SEL    5
#define PLEN   5
#define NCLS   100
#define PSTRIDE 224

// ---------------- scratch (static device allocations; harness-legal) ----------------
__device__ float g_x   [BATCH * SMAX * DMODEL];
__device__ float g_x0  [BATCH * S1   * DMODEL];
__device__ float g_h   [BATCH * SMAX * DMODEL];
__device__ float g_qkv [BATCH * SMAX * 3 * DMODEL];
__device__ float g_o   [BATCH * SMAX * DMODEL];
__device__ float g_mlp [BATCH * SMAX * MLPD];
__device__ float g_p   [BATCH * NHEAD * PSTRIDE * PSTRIDE];
__device__ float g_feat[BATCH * DMODEL];
__device__ float g_score[BATCH * POOL];
__device__ float g_lognorm[POOL];
__device__ float g_logwn[POOL];
__device__ int   g_topk[BATCH * SEL];

// ---------------- reductions (blockDim == 256 assumed) ----------------
__device__ __forceinline__ float block_sum256(float v, float* red) {
    int lane = threadIdx.x & 31, wid = threadIdx.x >> 5;
    #pragma unroll
    for (int o = 16; o; o >>= 1) v += __shfl_xor_sync(0xffffffffu, v, o);
    if (lane == 0) red[wid] = v;
    __syncthreads();
    float r = (lane < 8) ? red[lane] : 0.f;
    #pragma unroll
    for (int o = 4; o; o >>= 1) r += __shfl_xor_sync(0xffffffffu, r, o);
    r = __shfl_sync(0xffffffffu, r, 0);
    __syncthreads();
    return r;
}

__device__ __forceinline__ float block_max256(float v, float* red) {
    int lane = threadIdx.x & 31, wid = threadIdx.x >> 5;
    #pragma unroll
    for (int o = 16; o; o >>= 1) v = fmaxf(v, __shfl_xor_sync(0xffffffffu, v, o));
    if (lane == 0) red[wid] = v;
    __syncthreads();
    float r = (lane < 8) ? red[lane] : -1e30f;
    #pragma unroll
    for (int o = 4; o; o >>= 1) r = fmaxf(r, __shfl_xor_sync(0xffffffffu, r, o));
    r = __shfl_sync(0xffffffffu, r, 0);
    __syncthreads();
    return r;
}

// ---------------- tf32 helpers ----------------
__device__ __forceinline__ uint32_t f2tf32(float x) {
    uint32_t u;
    asm("cvt.rna.tf32.f32 %0, %1;" : "=r"(u) : "f"(x));
    return u;
}

__device__ __forceinline__ void mma_tf32(float* c, const uint32_t* a, uint32_t b0, uint32_t b1) {
    asm volatile(
        "mma.sync.aligned.m16n8k8.row.col.f32.tf32.tf32.f32 "
        "{%0,%1,%2,%3}, {%4,%5,%6,%7}, {%8,%9}, {%0,%1,%2,%3};"
        : "+f"(c[0]), "+f"(c[1]), "+f"(c[2]), "+f"(c[3])
        : "r"(a[0]), "r"(a[1]), "r"(a[2]), "r"(a[3]), "r"(b0), "r"(b1));
}

__device__ __forceinline__ void cp_async16(void* smem_dst, const void* gsrc, int src_bytes) {
    unsigned sa = (unsigned)__cvta_generic_to_shared(smem_dst);
    asm volatile("cp.async.cg.shared.global [%0], [%1], 16, %2;"
                 :: "r"(sa), "l"(gsrc), "r"(src_bytes));
}
__device__ __forceinline__ void cp_commit() {
    asm volatile("cp.async.commit_group;");
}

// ---------------- pipelined tf32 tensor-core GEMM ----------------
// C[M,N] = A[M,K] @ W[K,N] + bias;  mode 0 = store, 1 = GELU store, 2 = add into C
// N % 128 == 0, K % 32 == 0; M guarded via cp.async zfill + epilogue guard.
#define TBM 128
#define TBN 128
#define TBK 32
#define APITCH 36     // 32 k + pad, 144B rows (16B aligned, conflict-free frags)
#define WPITCH 136    // 128 n + pad, 544B rows
#define GEMM_SMEM ((2 * TBM * APITCH + 2 * TBK * WPITCH) * 4)

__global__ void __launch_bounds__(256) tc_gemm_kernel(
    const float* __restrict__ A, const float* __restrict__ W,
    const float* __restrict__ bias, float* __restrict__ C,
    int M, int N, int K, int mode)
{
    extern __shared__ float smem[];
    float* As = smem;                       // [2][TBM][APITCH]
    float* Ws = smem + 2 * TBM * APITCH;    // [2][TBK][WPITCH]

    int tid  = threadIdx.x;
    int warp = tid >> 5, lane = tid & 31;
    int g = lane >> 2, tig = lane & 3;
    int wm = (warp & 1) * 64;
    int wn = (warp >> 1) * 32;
    int row0 = blockIdx.y * TBM;
    int col0 = blockIdx.x * TBN;

    float acc[4][4][4];
    #pragma unroll
    for (int mt = 0; mt < 4; mt++)
        #pragma unroll
        for (int nt = 0; nt < 4; nt++)
            #pragma unroll
            for (int i = 0; i < 4; i++) acc[mt][nt][i] = 0.f;

    // tile loader: issues 8 cp.async per thread (A: 4, W: 4)
    auto load_tiles = [&](int k0, int buf) {
        float* Ab = As + buf * TBM * APITCH;
        float* Wb = Ws + buf * TBK * WPITCH;
        #pragma unroll
        for (int i = 0; i < 4; i++) {
            int slot = tid + i * 256;         // 0..1023
            int r  = slot >> 3;               // 0..127
            int c4 = (slot & 7) * 4;          // 0..28
            int gm = row0 + r;
            const float* src = A + (size_t)gm * K + k0 + c4;
            cp_async16(&Ab[r * APITCH + c4], src, (gm < M) ? 16 : 0);
        }
        #pragma unroll
        for (int i = 0; i < 4; i++) {
            int slot = tid + i * 256;
            int kr = slot >> 5;               // 0..31
            int nc = (slot & 31) * 4;         // 0..124
            const float* src = W + (size_t)(k0 + kr) * N + col0 + nc;
            cp_async16(&Wb[kr * WPITCH + nc], src, 16);
        }
        cp_commit();
    };

    int T = K / TBK;
    load_tiles(0, 0);

    for (int t = 0; t < T; t++) {
        int buf = t & 1;
        if (t + 1 < T) {
            load_tiles((t + 1) * TBK, (t + 1) & 1);
            asm volatile("cp.async.wait_group 1;");
        } else {
            asm volatile("cp.async.wait_group 0;");
        }
        __syncthreads();

        const float* Ab = As + buf * TBM * APITCH;
        const float* Wb = Ws + buf * TBK * WPITCH;
        #pragma unroll
        for (int ks = 0; ks < 4; ks++) {
            int kk = ks * 8;
            uint32_t af[4][4];
            #pragma unroll
            for (int mt = 0; mt < 4; mt++) {
                int m0 = wm + mt * 16;
                af[mt][0] = f2tf32(Ab[(m0 + g    ) * APITCH + kk + tig    ]);
                af[mt][1] = f2tf32(Ab[(m0 + g + 8) * APITCH + kk + tig    ]);
                af[mt][2] = f2tf32(Ab[(m0 + g    ) * APITCH + kk + tig + 4]);
                af[mt][3] = f2tf32(Ab[(m0 + g + 8) * APITCH + kk + tig + 4]);
            }
            #pragma unroll
            for (int nt = 0; nt < 4; nt++) {
                int n0 = wn + nt * 8;
                uint32_t b0 = f2tf32(Wb[(kk + tig    ) * WPITCH + n0 + g]);
                uint32_t b1 = f2tf32(Wb[(kk + tig + 4) * WPITCH + n0 + g]);
                #pragma unroll
                for (int mt = 0; mt < 4; mt++)
                    mma_tf32(acc[mt][nt], af[mt], b0, b1);
            }
        }
        __syncthreads();
    }

    #pragma unroll
    for (int mt = 0; mt < 4; mt++) {
        #pragma unroll
        for (int nt = 0; nt < 4; nt++) {
            int gn = col0 + wn + nt * 8 + tig * 2;
            #pragma unroll
            for (int half = 0; half < 2; half++) {
                int gm = row0 + wm + mt * 16 + g + half * 8;
                if (gm >= M) continue;
                #pragma unroll
                for (int cc = 0; cc < 2; cc++) {
                    float v = acc[mt][nt][half * 2 + cc] + bias[gn + cc];
                    if (mode == 1) v = 0.5f * v * (1.0f + erff(v * 0.70710678118654752f));
                    size_t off = (size_t)gm * N + gn + cc;
                    if (mode == 2) C[off] += v;
                    else C[off] = v;
                }
            }
        }
    }
}

// ---------------- LayerNorm over 768 (= 3*256) ----------------
__global__ void ln_kernel(const float* __restrict__ in, float* __restrict__ out,
                          const float* __restrict__ w, const float* __restrict__ b,
                          long long in_stride, long long out_stride)
{
    __shared__ float red[8];
    const float* x = in + (long long)blockIdx.x * in_stride;
    float* y = out + (long long)blockIdx.x * out_stride;
    int t = threadIdx.x;
    float v0 = x[t], v1 = x[t + 256], v2 = x[t + 512];
    float mean = block_sum256(v0 + v1 + v2, red) * (1.f / 768.f);
    float d0 = v0 - mean, d1 = v1 - mean, d2 = v2 - mean;
    float var = block_sum256(d0 * d0 + d1 * d1 + d2 * d2, red) * (1.f / 768.f);
    float rstd = rsqrtf(var + 1e-6f);
    y[t]       = d0 * rstd * w[t]       + b[t];
    y[t + 256] = d1 * rstd * w[t + 256] + b[t + 256];
    y[t + 512] = d2 * rstd * w[t + 512] + b[t + 512];
}

// ---------------- attention (coalesced, smem-tiled, P materialized) ----------------
#define SPAD 68

__global__ void __launch_bounds__(256) score_kernel(const float* __restrict__ qkv, int S)
{
    __shared__ float Qs[32][SPAD];
    __shared__ float KsT[64][SPAD];   // [d][k] transposed
    int q0 = blockIdx.x * 32, h = blockIdx.y, b = blockIdx.z;
    int tid = threadIdx.x;
    int q = tid >> 3, kg = tid & 7;
    const float* base = qkv + (size_t)b * S * (3 * DMODEL) + h * HDIM;
    float* prow = g_p + (((size_t)b * NHEAD + h) * PSTRIDE) * PSTRIDE;

    #pragma unroll
    for (int i = 0; i < 2; i++) {
        int slot = tid + i * 256;
        int r = slot >> 4, c4 = (slot & 15) * 4;
        int gq = q0 + r;
        float4 v = make_float4(0.f, 0.f, 0.f, 0.f);
        if (gq < S) v = *reinterpret_cast<const float4*>(&base[(size_t)gq * (3 * DMODEL) + c4]);
        *reinterpret_cast<float4*>(&Qs[r][c4]) = v;
    }

    int ntile = (S + 63) >> 6;
    for (int kt = 0; kt < ntile; kt++) {
        int k0 = kt * 64;
        #pragma unroll
        for (int i = 0; i < 4; i++) {
            int slot = tid + i * 256;
            int r = slot >> 4, c4 = (slot & 15) * 4;
            int gk = k0 + r;
            float4 v = make_float4(0.f, 0.f, 0.f, 0.f);
            if (gk < S) v = *reinterpret_cast<const float4*>(&base[(size_t)gk * (3 * DMODEL) + DMODEL + c4]);
            KsT[c4 + 0][r] = v.x;
            KsT[c4 + 1][r] = v.y;
            KsT[c4 + 2][r] = v.z;
            KsT[c4 + 3][r] = v.w;
        }
        __syncthreads();

        float acc[8];
        #pragma unroll
        for (int j = 0; j < 8; j++) acc[j] = 0.f;
        #pragma unroll
        for (int d = 0; d < HDIM; d++) {
            float qa = Qs[q][d];
            const float* kr = &KsT[d][kg * 8];
            #pragma unroll
            for (int j = 0; j < 8; j++) acc[j] += qa * kr[j];
        }
        int gq = q0 + q;
        if (gq < S) {
            float* pw = prow + (size_t)gq * PSTRIDE + k0 + kg * 8;
            #pragma unroll
            for (int j = 0; j < 8; j++) {
                int gk = k0 + kg * 8 + j;
                if (gk < S) pw[j] = acc[j] * 0.125f;
            }
        }
        __syncthreads();
    }
}

__global__ void softmax_kernel(int S)
{
    __shared__ float red[8];
    int q = blockIdx.x, h = blockIdx.y, b = blockIdx.z;
    float* prow = g_p + ((((size_t)b * NHEAD + h) * PSTRIDE) + q) * PSTRIDE;
    int t = threadIdx.x;
    float v = (t < S) ? prow[t] : -1e30f;
    float mx = block_max256(v, red);
    float e = (t < S) ? expf(v - mx) : 0.f;
    float sum = block_sum256(e, red);
    if (t < S) prow[t] = e / sum;
}

__global__ void __launch_bounds__(256) pv_kernel(const float* __restrict__ qkv,
                                                 float* __restrict__ o, int S)
{
    __shared__ float Ps[32][SPAD];
    __shared__ float Vs[64][SPAD];
    int q0 = blockIdx.x * 32, h = blockIdx.y, b = blockIdx.z;
    int tid = threadIdx.x;
    int q = tid >> 3, dg = tid & 7;
    const float* vbase = qkv + (size_t)b * S * (3 * DMODEL) + 2 * DMODEL + h * HDIM;
    const float* prow = g_p + (((size_t)b * NHEAD + h) * PSTRIDE) * PSTRIDE;

    float acc[8];
    #pragma unroll
    for (int j = 0; j < 8; j++) acc[j] = 0.f;

    int ntile = (S + 63) >> 6;
    for (int kt = 0; kt < ntile; kt++) {
        int k0 = kt * 64;
        #pragma unroll
        for (int i = 0; i < 2; i++) {
            int slot = tid + i * 256;
            int r = slot >> 4, c4 = (slot & 15) * 4;
            int gq = q0 + r;
            float4 v = make_float4(0.f, 0.f, 0.f, 0.f);
            if (gq < S) {
                #pragma unroll
                for (int c = 0; c < 4; c++) {
                    int gk = k0 + c4 + c;
                    ((float*)&v)[c] = (gk < S) ? prow[(size_t)gq * PSTRIDE + gk] : 0.f;
                }
            }
            *reinterpret_cast<float4*>(&Ps[r][c4]) = v;
        }
        #pragma unroll
        for (int i = 0; i < 4; i++) {
            int slot = tid + i * 256;
            int r = slot >> 4, c4 = (slot & 15) * 4;
            int gk = k0 + r;
            float4 v = make_float4(0.f, 0.f, 0.f, 0.f);
            if (gk < S) v = *reinterpret_cast<const float4*>(&vbase[(size_t)gk * (3 * DMODEL) + c4]);
            *reinterpret_cast<float4*>(&Vs[r][c4]) = v;
        }
        __syncthreads();

        #pragma unroll
        for (int k = 0; k < 64; k++) {
            float p = Ps[q][k];
            const float* vr = &Vs[k][dg * 8];
            #pragma unroll
            for (int j = 0; j < 8; j++) acc[j] += p * vr[j];
        }
        __syncthreads();
    }

    int gq = q0 + q;
    if (gq < S) {
        float* ow = o + ((size_t)(b * S + gq)) * DMODEL + h * HDIM + dg * 8;
        #pragma unroll
        for (int j = 0; j < 8; j++) ow[j] = acc[j];
    }
}

// ---------------- patchify + embedding ----------------
__global__ void patchify_kernel(const float* __restrict__ in)
{
    size_t i = (size_t)blockIdx.x * 256 + threadIdx.x;
    if (i >= (size_t)BATCH * 196 * DMODEL) return;
    int v = (int)(i % DMODEL);
    size_t t = i / DMODEL;
    int p = (int)(t % 196);
    int b = (int)(t / 196);
    int c = v >> 8;
    int py = (v & 255) >> 4;
    int px = v & 15;
    int gy = p / 14, gx = p % 14;
    g_mlp[i] = in[(((size_t)b * 3 + c) * 224 + gy * 16 + py) * 224 + gx * 16 + px];
}

__global__ void embed_kernel(const float* __restrict__ cls, const float* __restrict__ pos)
{
    size_t i = (size_t)blockIdx.x * 256 + threadIdx.x;
    if (i >= (size_t)BATCH * S1 * DMODEL) return;
    int d = (int)(i % DMODEL);
    size_t t = i / DMODEL;
    int s = (int)(t % S1);
    int b = (int)(t / S1);
    float v;
    if (s == 0) v = cls[d] + pos[d];
    else        v = g_o[((size_t)b * 196 + (s - 1)) * DMODEL + d] + pos[(size_t)s * DMODEL + d];
    g_x[i] = v;
    g_x0[i] = v;
}

// ---------------- routing ----------------
__global__ void pool_stats_kernel(const float* __restrict__ var)
{
    __shared__ float red[8];
    int p = blockIdx.x;
    const float* v = var + (size_t)p * DMODEL * DMODEL;
    float s = 0.f;
    for (int i = threadIdx.x; i < DMODEL * DMODEL; i += 256) { float t = v[i]; s += t * t; }
    float tot = block_sum256(s, red);
    if (threadIdx.x == 0) g_lognorm[p] = 0.25f * logf(tot);
}

__global__ void logwn_kernel(const float* __restrict__ freq)
{
    float m = freq[0];
    for (int i = 1; i < POOL; i++) m = fmaxf(m, freq[i]);
    float w[POOL]; float ss = 0.f;
    for (int i = 0; i < POOL; i++) { w[i] = m - freq[i]; ss += w[i] * w[i]; }
    float nz = fmaxf(sqrtf(ss), 1e-12f);
    for (int i = 0; i < POOL; i++) g_logwn[i] = logf(fmaxf(w[i] / nz, 1e-30f));
}

__global__ void quad_kernel(const float* __restrict__ keys, const float* __restrict__ inv_var)
{
    __shared__ float diff[DMODEL];
    __shared__ float red[8];
    int b = blockIdx.x, p = blockIdx.y;
    for (int i = threadIdx.x; i < DMODEL; i += 256)
        diff[i] = g_feat[b * DMODEL + i] - keys[p * DMODEL + i];
    __syncthreads();
    const float* M = inv_var + (size_t)p * DMODEL * DMODEL;
    float acc = 0.f;
    #pragma unroll
    for (int ei = 0; ei < 3; ei++) {
        int e = threadIdx.x + ei * 256;
        float inner = 0.f;
        for (int d = 0; d < DMODEL; d++)
            inner += diff[d] * M[(size_t)d * DMODEL + e];
        acc += inner * diff[e];
    }
    float quad = block_sum256(acc, red);
    if (threadIdx.x == 0)
        g_score[b * POOL + p] = -0.5f * quad + g_lognorm[p] + g_logwn[p];
}

__global__ void topk_kernel()
{
    int b = threadIdx.x;
    if (b >= BATCH) return;
    float s[POOL]; bool used[POOL];
    for (int p = 0; p < POOL; p++) { s[p] = g_score[b * POOL + p]; used[p] = false; }
    for (int i = 0; i < SEL; i++) {
        int best = 0; float bv = 3.0e38f;
        for (int p = 0; p < POOL; p++)
            if (!used[p] && s[p] < bv) { bv = s[p]; best = p; }
        used[best] = true;
        g_topk[b * SEL + i] = best;
    }
}

__global__ void build_sx_kernel(const float* __restrict__ prompts, const float* __restrict__ pos)
{
    size_t i = (size_t)blockIdx.x * 256 + threadIdx.x;
    if (i >= (size_t)BATCH * SMAX * DMODEL) return;
    int d = (int)(i % DMODEL);
    size_t t = i / DMODEL;
    int s = (int)(t % SMAX);
    int b = (int)(t / SMAX);
    float v;
    if (s == 0) {
        v = g_x0[(size_t)b * S1 * DMODEL + d];
    } else if (s <= SEL * PLEN) {
        int idx = s - 1;
        int pi = idx / PLEN, j = idx % PLEN;
        int pool = g_topk[b * SEL + pi];
        v = prompts[((size_t)pool * PLEN + j) * DMODEL + d] + pos[d];
    } else {
        v = g_x0[((size_t)b * S1 + (s - SEL * PLEN)) * DMODEL + d];
    }
    g_x[i] = v;
}

// ---------------- epilogue ----------------
__global__ void feat_kernel()
{
    int i = blockIdx.x * 256 + threadIdx.x;
    if (i >= BATCH * DMODEL) return;
    int b = i / DMODEL, d = i % DMODEL;
    float s = 0.f;
    for (int t = 1; t <= SEL * PLEN; t++)
        s += g_h[((size_t)b * SMAX + t) * DMODEL + d];
    g_feat[i] = s * (1.f / (SEL * PLEN));
}

__global__ void head_kernel(const float* __restrict__ hw, const float* __restrict__ hb,
                            float* __restrict__ out)
{
    int i = blockIdx.x * 256 + threadIdx.x;
    if (i >= BATCH * NCLS) return;
    int b = i / NCLS, n = i % NCLS;
    float acc = hb[n];
    for (int k = 0; k < DMODEL; k++) acc += g_feat[b * DMODEL + k] * hw[k * NCLS + n];
    out[i] = acc;
}

// ---------------- host orchestration ----------------
static void run_vit(int S, int M,
    const float* ln1w, const float* ln1b, const float* qkvw, const float* qkvb,
    const float* pw, const float* pb, const float* ln2w, const float* ln2b,
    const float* f1w, const float* f1b, const float* f2w, const float* f2b,
    float* px, float* ph, float* pqkv, float* po, float* pmlp)
{
    int gy = (M + TBM - 1) / TBM;
    int qt = (S + 31) / 32;
    for (int l = 0; l < NLAYER; l++) {
        ln_kernel<<<M, 256>>>(px, ph, ln1w + (size_t)l * DMODEL, ln1b + (size_t)l * DMODEL, DMODEL, DMODEL);
        tc_gemm_kernel<<<dim3(3 * DMODEL / TBN, gy), 256, GEMM_SMEM>>>(ph, qkvw + (size_t)l * DMODEL * 3 * DMODEL,
                                                            qkvb + (size_t)l * 3 * DMODEL, pqkv, M, 3 * DMODEL, DMODEL, 0);
        score_kernel<<<dim3(qt, NHEAD, BATCH), 256>>>(pqkv, S);
        softmax_kernel<<<dim3(S, NHEAD, BATCH), 256>>>(S);
        pv_kernel<<<dim3(qt, NHEAD, BATCH), 256>>>(pqkv, po, S);
        tc_gemm_kernel<<<dim3(DMODEL / TBN, gy), 256, GEMM_SMEM>>>(po, pw + (size_t)l * DMODEL * DMODEL,
                                                        pb + (size_t)l * DMODEL, px, M, DMODEL, DMODEL, 2);
        ln_kernel<<<M, 256>>>(px, ph, ln2w + (size_t)l * DMODEL, ln2b + (size_t)l * DMODEL, DMODEL, DMODEL);
        tc_gemm_kernel<<<dim3(MLPD / TBN, gy), 256, GEMM_SMEM>>>(ph, f1w + (size_t)l * DMODEL * MLPD,
                                                      f1b + (size_t)l * MLPD, pmlp, M, MLPD, DMODEL, 1);
        tc_gemm_kernel<<<dim3(DMODEL / TBN, gy), 256, GEMM_SMEM>>>(pmlp, f2w + (size_t)l * MLPD * DMODEL,
                                                        f2b + (size_t)l * DMODEL, px, M, DMODEL, MLPD, 2);
    }
}

extern "C" void kernel_launch(void* const* d_in, const int* in_sizes, int n_in,
                              void* d_out, int out_size)
{
    const float* inputs    = (const float*)d_in[0];
    const float* patch_w   = (const float*)d_in[1];
    const float* patch_b   = (const float*)d_in[2];
    const float* cls_token = (const float*)d_in[3];
    const float* pos_embed = (const float*)d_in[4];
    const float* ln1_w = (const float*)d_in[5];
    const float* ln1_b = (const float*)d_in[6];
    const float* qkv_w = (const float*)d_in[7];
    const float* qkv_b = (const float*)d_in[8];
    const float* proj_w = (const float*)d_in[9];
    const float* proj_b = (const float*)d_in[10];
    const float* ln2_w = (const float*)d_in[11];
    const float* ln2_b = (const float*)d_in[12];
    const float* fc1_w = (const float*)d_in[13];
    const float* fc1_b = (const float*)d_in[14];
    const float* fc2_w = (const float*)d_in[15];
    const float* fc2_b = (const float*)d_in[16];
    const float* norm_w = (const float*)d_in[17];
    const float* norm_b = (const float*)d_in[18];
    const float* head_w = (const float*)d_in[19];
    const float* head_b = (const float*)d_in[20];
    const float* key_pool = (const float*)d_in[21];
    const float* frequency = (const float*)d_in[22];
    const float* prompts = (const float*)d_in[23];
    const float* variance = (const float*)d_in[24];
    const float* inv_variance = (const float*)d_in[25];

    static bool attr_set = false;
    if (!attr_set) {
        cudaFuncSetAttribute(tc_gemm_kernel, cudaFuncAttributeMaxDynamicSharedMemorySize, GEMM_SMEM);
        attr_set = true;
    }

    float *px, *ph, *pqkv, *po, *pmlp, *pfeat;
    cudaGetSymbolAddress((void**)&px,   g_x);
    cudaGetSymbolAddress((void**)&ph,   g_h);
    cudaGetSymbolAddress((void**)&pqkv, g_qkv);
    cudaGetSymbolAddress((void**)&po,   g_o);
    cudaGetSymbolAddress((void**)&pmlp, g_mlp);
    cudaGetSymbolAddress((void**)&pfeat, g_feat);

    // 1) patch embed
    patchify_kernel<<<(BATCH * 196 * DMODEL + 255) / 256, 256>>>(inputs);
    tc_gemm_kernel<<<dim3(DMODEL / TBN, (BATCH * 196 + TBM - 1) / TBM), 256, GEMM_SMEM>>>(
        pmlp, patch_w, patch_b, po, BATCH * 196, DMODEL, DMODEL, 0);
    embed_kernel<<<(BATCH * S1 * DMODEL + 255) / 256, 256>>>(cls_token, pos_embed);

    // 2) first ViT pass (S=197)
    run_vit(S1, BATCH * S1, ln1_w, ln1_b, qkv_w, qkv_b, proj_w, proj_b,
            ln2_w, ln2_b, fc1_w, fc1_b, fc2_w, fc2_b, px, ph, pqkv, po, pmlp);

    // 3) routing
    ln_kernel<<<BATCH, 256>>>(px, pfeat, norm_w, norm_b, (long long)S1 * DMODEL, DMODEL);
    pool_stats_kernel<<<POOL, 256>>>(variance);
    logwn_kernel<<<1, 1>>>(frequency);
    quad_kernel<<<dim3(BATCH, POOL), 256>>>(key_pool, inv_variance);
    topk_kernel<<<1, 32>>>();

    // 4) splice prompts (S=222)
    build_sx_kernel<<<(BATCH * SMAX * DMODEL + 255) / 256, 256>>>(prompts, pos_embed);

    // 5) second ViT pass (S=222)
    run_vit(SMAX, BATCH * SMAX, ln1_w, ln1_b, qkv_w, qkv_b, proj_w, proj_b,
            ln2_w, ln2_b, fc1_w, fc1_b, fc2_w, fc2_b, px, ph, pqkv, po, pmlp);

    // 6) final LN, mean over prompt tokens, head
    ln_kernel<<<BATCH * SMAX, 256>>>(px, ph, norm_w, norm_b, DMODEL, DMODEL);
    feat_kernel<<<(BATCH * DMODEL + 255) / 256, 256>>>();
    head_kernel<<<(BATCH * NCLS + 255) / 256, 256>>>(head_w, head_b, (float*)d_out);
}